// round 7
// baseline (speedup 1.0000x reference)
#include <cuda_runtime.h>
#include <cstdint>

// Problem constants (fixed by the reference setup)
#define B_    4
#define CIN_  64
#define COUT_ 64
#define N_    16384
#define K_    8
#define TILE_ 32    // points per tile in the main kernel
#define NTILES_ (B_ * N_ / TILE_)   // 2048
#define GRID_MAIN_ 296              // 148 SMs x 2 CTAs, one full wave

// Scratch accumulator, point-major: [b][n][o]  (16.8 MB, L2-resident).
// Invariant: zero at kernel_launch entry. Zeroed at module load (.bss) for the
// first call; finalize_kernel re-zeroes it after consuming, keeping every
// graph replay identical.
__device__ float g_scratch[(size_t)B_ * N_ * COUT_];

// ---------- packed f32x2 helpers (full-rate FFMA path on sm_103a) ----------
__device__ __forceinline__ unsigned long long pk2(float lo, float hi) {
    unsigned long long r;
    asm("mov.b64 %0, {%1, %2};" : "=l"(r) : "f"(lo), "f"(hi));
    return r;
}
__device__ __forceinline__ float2 upk2(unsigned long long v) {
    float2 r;
    asm("mov.b64 {%0, %1}, %2;" : "=f"(r.x), "=f"(r.y) : "l"(v));
    return r;
}
__device__ __forceinline__ unsigned long long ffma2(unsigned long long a,
                                                    unsigned long long b,
                                                    unsigned long long c) {
    unsigned long long r;
    asm("fma.rn.f32x2 %0, %1, %2, %3;" : "=l"(r) : "l"(a), "l"(b), "l"(c));
    return r;
}

// ---------- kernel 1: persistent fused ft-compute + edge scatter ----------
// 296 persistent blocks of 256 threads; each block loads the 64 KB weight
// image into smem ONCE, then loops over ~7 tiles of 32 points.
//   smem: sW[4][64][64] weights (theta d=0..2, wb as d=3)  = 64 KB
//         sF[64][32]    features of the tile               =  8 KB
//         sE[32][8][4]  per-edge {idx, dx, dy, dz}         =  4 KB
// Compute mapping: og = tid&15 -> 4 consecutive o's; pg = tid>>4 -> 2 points.
// Scatter: red.global.add.v4.f32 into the target point's contiguous scratch row.
__global__ __launch_bounds__(256, 2)
void flexconv_main_kernel(const float* __restrict__ feat,
                          const float* __restrict__ theta,
                          const float* __restrict__ wbias,
                          const int*   __restrict__ nbh,
                          const float* __restrict__ pos)
{
    extern __shared__ float smem[];
    float* sW = smem;                       // 16384 floats
    float* sF = sW + 4 * CIN_ * COUT_;      // 2048 floats
    float* sE = sF + CIN_ * TILE_;          // 1024 floats

    const int tid = threadIdx.x;

    // --- load weights ONCE: theta [d][i][o] for d=0..2, wb appended as d=3 ---
    {
        float4* w4 = (float4*)sW;
        const float4* t4 = (const float4*)theta;     // 3072 float4
        #pragma unroll
        for (int j = 0; j < 12; j++) w4[j * 256 + tid] = t4[j * 256 + tid];
        const float4* b4 = (const float4*)wbias;     // 1024 float4
        #pragma unroll
        for (int j = 0; j < 4; j++)  w4[3072 + j * 256 + tid] = b4[j * 256 + tid];
    }

    const int og = tid & 15;
    const int pg = tid >> 4;
    const int o4 = og * 4;

    for (int t = blockIdx.x; t < NTILES_; t += GRID_MAIN_) {
        const int b  = t >> 9;              // 512 tiles per batch
        const int n0 = (t & 511) * TILE_;

        // Orders weight load on first iter, protects sF/sE reuse on later iters.
        __syncthreads();

        // --- load features: sF[i][p] = feat[b, i, n0+p] ---
        {
            const int p = tid & 31, i0 = tid >> 5;
            const float* fb = feat + (size_t)b * CIN_ * N_ + n0 + p;
            #pragma unroll
            for (int j = 0; j < 8; j++) {
                int i = i0 * 8 + j;
                sF[i * TILE_ + p] = fb[(size_t)i * N_];
            }
        }
        // --- build edges: one thread per (p, k) ---
        {
            const int p = tid & 31, k = tid >> 5;
            const int n = n0 + p;
            const int idx = nbh[((size_t)b * K_ + k) * N_ + n];
            const float* pb = pos + (size_t)b * 3 * N_;
            float dx = pb[idx]          - pb[n];
            float dy = pb[N_ + idx]     - pb[N_ + n];
            float dz = pb[2 * N_ + idx] - pb[2 * N_ + n];
            *(float4*)(sE + (p * K_ + k) * 4) =
                make_float4(__int_as_float(idx), dx, dy, dz);
        }
        __syncthreads();

        // acc[d][pt][half] : half 0 = o4..o4+1, half 1 = o4+2..o4+3 (f32x2)
        unsigned long long acc[4][2][2];
        #pragma unroll
        for (int d = 0; d < 4; d++)
            #pragma unroll
            for (int pt = 0; pt < 2; pt++)
                acc[d][pt][0] = acc[d][pt][1] = 0ULL;

        const float* fPtr = sF + pg * 2;
        #pragma unroll 8
        for (int i = 0; i < CIN_; i++) {
            float2 fv = *(const float2*)(fPtr + i * TILE_);  // 2 points' feature i
            unsigned long long f0 = pk2(fv.x, fv.x);
            unsigned long long f1 = pk2(fv.y, fv.y);
            const float* wPtr = sW + i * COUT_ + o4;
            #pragma unroll
            for (int d = 0; d < 4; d++) {
                ulonglong2 w = *(const ulonglong2*)(wPtr + d * CIN_ * COUT_);
                acc[d][0][0] = ffma2(w.x, f0, acc[d][0][0]);
                acc[d][0][1] = ffma2(w.y, f0, acc[d][0][1]);
                acc[d][1][0] = ffma2(w.x, f1, acc[d][1][0]);
                acc[d][1][1] = ffma2(w.y, f1, acc[d][1][1]);
            }
        }

        // --- scatter: val = dx*ft0 + dy*ft1 + dz*ft2 + fb per edge ---
        const size_t sbase = (size_t)b * N_;
        #pragma unroll
        for (int pt = 0; pt < 2; pt++) {
            const int p = pg * 2 + pt;
            #pragma unroll
            for (int k = 0; k < K_; k++) {
                float4 e = *(const float4*)(sE + (p * K_ + k) * 4);
                const int idx = __float_as_int(e.x);
                unsigned long long dx2 = pk2(e.y, e.y);
                unsigned long long dy2 = pk2(e.z, e.z);
                unsigned long long dz2 = pk2(e.w, e.w);
                unsigned long long v0 = ffma2(acc[0][pt][0], dx2,
                                        ffma2(acc[1][pt][0], dy2,
                                        ffma2(acc[2][pt][0], dz2, acc[3][pt][0])));
                unsigned long long v1 = ffma2(acc[0][pt][1], dx2,
                                        ffma2(acc[1][pt][1], dy2,
                                        ffma2(acc[2][pt][1], dz2, acc[3][pt][1])));
                float2 a = upk2(v0), c = upk2(v1);
                float* dst = g_scratch + ((sbase + (size_t)idx) * COUT_ + o4);
                asm volatile("red.global.add.v4.f32 [%0], {%1, %2, %3, %4};"
                             :: "l"(dst), "f"(a.x), "f"(a.y), "f"(c.x), "f"(c.y)
                             : "memory");
            }
        }
    }
}

// ---------- kernel 2: transpose scratch [b][n][o] -> out [b][o][n], add bias,
//            then re-zero this block's scratch region (self-cleaning) ----------
__global__ __launch_bounds__(256)
void finalize_kernel(float* __restrict__ out, const float* __restrict__ bias)
{
    __shared__ float s[64 * 65];   // padded to avoid bank conflicts
    const int tid = threadIdx.x;
    const int b   = blockIdx.y;
    const int n0  = blockIdx.x * 64;

    float* region = g_scratch + ((size_t)b * N_ + n0) * COUT_;  // 64x64 floats

    {   // phase 1: coalesced-in-o loads (L2 hits on scratch)
        const int o = tid & 63, r0 = tid >> 6;
        const float* src = region + o;
        #pragma unroll
        for (int j = 0; j < 16; j++) {
            int nn = r0 * 16 + j;
            s[nn * 65 + o] = src[(size_t)nn * COUT_];
        }
    }
    __syncthreads();   // all reads of the region complete

    {   // phase 2: vector-zero this block's scratch region for the next call
        float4* r4 = (float4*)region;      // 1024 float4
        #pragma unroll
        for (int j = 0; j < 4; j++)
            r4[j * 256 + tid] = make_float4(0.f, 0.f, 0.f, 0.f);
    }

    {   // phase 3: coalesced-in-n stores to the output layout + bias
        const int nn = tid & 63, o0 = tid >> 6;
        float* dstb = out + (size_t)b * COUT_ * N_ + n0 + nn;
        #pragma unroll
        for (int j = 0; j < 16; j++) {
            int o = o0 * 16 + j;
            dstb[(size_t)o * N_] = s[nn * 65 + o] + bias[o];
        }
    }
}

// ---------- launch ----------
extern "C" void kernel_launch(void* const* d_in, const int* in_sizes, int n_in,
                              void* d_out, int out_size)
{
    // All six inputs have distinct element counts -> match by size.
    const float *feat = nullptr, *theta = nullptr, *wb = nullptr,
                *pos = nullptr, *bias = nullptr;
    const int* nbh = nullptr;
    for (int i = 0; i < n_in; i++) {
        switch (in_sizes[i]) {
            case B_ * CIN_ * N_:    feat  = (const float*)d_in[i]; break; // 4194304
            case 3 * CIN_ * COUT_:  theta = (const float*)d_in[i]; break; // 12288
            case CIN_ * COUT_:      wb    = (const float*)d_in[i]; break; // 4096
            case B_ * K_ * N_:      nbh   = (const int*)  d_in[i]; break; // 524288
            case B_ * 3 * N_:       pos   = (const float*)d_in[i]; break; // 196608
            case COUT_:             bias  = (const float*)d_in[i]; break; // 64
        }
    }

    const int smem_bytes = (4 * CIN_ * COUT_ + CIN_ * TILE_ + TILE_ * K_ * 4)
                           * (int)sizeof(float);   // 77824 B
    cudaFuncSetAttribute(flexconv_main_kernel,
                         cudaFuncAttributeMaxDynamicSharedMemorySize, smem_bytes);

    // 1) persistent fused compute + scatter (scratch is zero on entry)
    flexconv_main_kernel<<<GRID_MAIN_, 256, smem_bytes>>>(feat, theta, wb, nbh, pos);

    // 2) transpose + bias into the harness output, re-zero scratch
    finalize_kernel<<<dim3(N_ / 64, B_), 256>>>((float*)d_out, bias);
}

// round 8
// speedup vs baseline: 1.0075x; 1.0075x over previous
#include <cuda_runtime.h>
#include <cstdint>

// Problem constants (fixed by the reference setup)
#define B_    4
#define CIN_  64
#define COUT_ 64
#define N_    16384
#define K_    8
#define TILE_ 32    // points per tile in the main kernel
#define NTILES_ (B_ * N_ / TILE_)   // 2048
#define GRID_MAIN_ 296              // 148 SMs x 2 CTAs, one full wave

// Scratch accumulator, point-major: [b][n][o]  (16.8 MB, L2-resident).
// Invariant: zero at kernel_launch entry. Zeroed at module load (.bss) for the
// first call; finalize_kernel re-zeroes it after consuming, keeping every
// graph replay identical.
__device__ float g_scratch[(size_t)B_ * N_ * COUT_];

// ---------- packed f32x2 helpers (full-rate FFMA path on sm_103a) ----------
__device__ __forceinline__ unsigned long long pk2(float lo, float hi) {
    unsigned long long r;
    asm("mov.b64 %0, {%1, %2};" : "=l"(r) : "f"(lo), "f"(hi));
    return r;
}
__device__ __forceinline__ float2 upk2(unsigned long long v) {
    float2 r;
    asm("mov.b64 {%0, %1}, %2;" : "=f"(r.x), "=f"(r.y) : "l"(v));
    return r;
}
__device__ __forceinline__ unsigned long long ffma2(unsigned long long a,
                                                    unsigned long long b,
                                                    unsigned long long c) {
    unsigned long long r;
    asm("fma.rn.f32x2 %0, %1, %2, %3;" : "=l"(r) : "l"(a), "l"(b), "l"(c));
    return r;
}

// ---------- kernel 1: persistent fused ft-compute + edge scatter ----------
// 296 persistent blocks of 256 threads; each block loads the 64 KB weight
// image into smem ONCE, then loops over ~7 tiles of 32 points.
//   smem: sW[4][64][64] weights (theta d=0..2, wb as d=3)  = 64 KB
//         sF[64][32]    features of the tile               =  8 KB
//         sE[32][8][4]  per-edge {idx, dx, dy, dz}         =  4 KB
// Compute mapping: og = tid&15 -> 4 consecutive o's; pg = tid>>4 -> 2 points.
// Scatter: red.global.add.v4.f32 into the target point's contiguous scratch row.
__global__ __launch_bounds__(256, 2)
void flexconv_main_kernel(const float* __restrict__ feat,
                          const float* __restrict__ theta,
                          const float* __restrict__ wbias,
                          const int*   __restrict__ nbh,
                          const float* __restrict__ pos)
{
    extern __shared__ float smem[];
    float* sW = smem;                       // 16384 floats
    float* sF = sW + 4 * CIN_ * COUT_;      // 2048 floats
    float* sE = sF + CIN_ * TILE_;          // 1024 floats

    const int tid = threadIdx.x;

    // --- load weights ONCE: theta [d][i][o] for d=0..2, wb appended as d=3 ---
    {
        float4* w4 = (float4*)sW;
        const float4* t4 = (const float4*)theta;     // 3072 float4
        #pragma unroll
        for (int j = 0; j < 12; j++) w4[j * 256 + tid] = t4[j * 256 + tid];
        const float4* b4 = (const float4*)wbias;     // 1024 float4
        #pragma unroll
        for (int j = 0; j < 4; j++)  w4[3072 + j * 256 + tid] = b4[j * 256 + tid];
    }

    const int og = tid & 15;
    const int pg = tid >> 4;
    const int o4 = og * 4;

    for (int t = blockIdx.x; t < NTILES_; t += GRID_MAIN_) {
        const int b  = t >> 9;              // 512 tiles per batch
        const int n0 = (t & 511) * TILE_;

        // Orders weight load on first iter, protects sF/sE reuse on later iters.
        __syncthreads();

        // --- load features: sF[i][p] = feat[b, i, n0+p] ---
        {
            const int p = tid & 31, i0 = tid >> 5;
            const float* fb = feat + (size_t)b * CIN_ * N_ + n0 + p;
            #pragma unroll
            for (int j = 0; j < 8; j++) {
                int i = i0 * 8 + j;
                sF[i * TILE_ + p] = fb[(size_t)i * N_];
            }
        }
        // --- build edges: one thread per (p, k) ---
        {
            const int p = tid & 31, k = tid >> 5;
            const int n = n0 + p;
            const int idx = nbh[((size_t)b * K_ + k) * N_ + n];
            const float* pb = pos + (size_t)b * 3 * N_;
            float dx = pb[idx]          - pb[n];
            float dy = pb[N_ + idx]     - pb[N_ + n];
            float dz = pb[2 * N_ + idx] - pb[2 * N_ + n];
            *(float4*)(sE + (p * K_ + k) * 4) =
                make_float4(__int_as_float(idx), dx, dy, dz);
        }
        __syncthreads();

        // acc[d][pt][half] : half 0 = o4..o4+1, half 1 = o4+2..o4+3 (f32x2)
        unsigned long long acc[4][2][2];
        #pragma unroll
        for (int d = 0; d < 4; d++)
            #pragma unroll
            for (int pt = 0; pt < 2; pt++)
                acc[d][pt][0] = acc[d][pt][1] = 0ULL;

        const float* fPtr = sF + pg * 2;
        #pragma unroll 8
        for (int i = 0; i < CIN_; i++) {
            float2 fv = *(const float2*)(fPtr + i * TILE_);  // 2 points' feature i
            unsigned long long f0 = pk2(fv.x, fv.x);
            unsigned long long f1 = pk2(fv.y, fv.y);
            const float* wPtr = sW + i * COUT_ + o4;
            #pragma unroll
            for (int d = 0; d < 4; d++) {
                ulonglong2 w = *(const ulonglong2*)(wPtr + d * CIN_ * COUT_);
                acc[d][0][0] = ffma2(w.x, f0, acc[d][0][0]);
                acc[d][0][1] = ffma2(w.y, f0, acc[d][0][1]);
                acc[d][1][0] = ffma2(w.x, f1, acc[d][1][0]);
                acc[d][1][1] = ffma2(w.y, f1, acc[d][1][1]);
            }
        }

        // --- scatter: val = dx*ft0 + dy*ft1 + dz*ft2 + fb per edge ---
        const size_t sbase = (size_t)b * N_;
        #pragma unroll
        for (int pt = 0; pt < 2; pt++) {
            const int p = pg * 2 + pt;
            #pragma unroll
            for (int k = 0; k < K_; k++) {
                float4 e = *(const float4*)(sE + (p * K_ + k) * 4);
                const int idx = __float_as_int(e.x);
                unsigned long long dx2 = pk2(e.y, e.y);
                unsigned long long dy2 = pk2(e.z, e.z);
                unsigned long long dz2 = pk2(e.w, e.w);
                unsigned long long v0 = ffma2(acc[0][pt][0], dx2,
                                        ffma2(acc[1][pt][0], dy2,
                                        ffma2(acc[2][pt][0], dz2, acc[3][pt][0])));
                unsigned long long v1 = ffma2(acc[0][pt][1], dx2,
                                        ffma2(acc[1][pt][1], dy2,
                                        ffma2(acc[2][pt][1], dz2, acc[3][pt][1])));
                float2 a = upk2(v0), c = upk2(v1);
                float* dst = g_scratch + ((sbase + (size_t)idx) * COUT_ + o4);
                asm volatile("red.global.add.v4.f32 [%0], {%1, %2, %3, %4};"
                             :: "l"(dst), "f"(a.x), "f"(a.y), "f"(c.x), "f"(c.y)
                             : "memory");
            }
        }
    }
}

// ---------- kernel 2: transpose scratch [b][n][o] -> out [b][o][n], add bias,
//            then re-zero this block's scratch region (self-cleaning) ----------
__global__ __launch_bounds__(256)
void finalize_kernel(float* __restrict__ out, const float* __restrict__ bias)
{
    __shared__ float s[64 * 65];   // padded to avoid bank conflicts
    const int tid = threadIdx.x;
    const int b   = blockIdx.y;
    const int n0  = blockIdx.x * 64;

    float* region = g_scratch + ((size_t)b * N_ + n0) * COUT_;  // 64x64 floats

    {   // phase 1: coalesced-in-o loads (L2 hits on scratch)
        const int o = tid & 63, r0 = tid >> 6;
        const float* src = region + o;
        #pragma unroll
        for (int j = 0; j < 16; j++) {
            int nn = r0 * 16 + j;
            s[nn * 65 + o] = src[(size_t)nn * COUT_];
        }
    }
    __syncthreads();   // all reads of the region complete

    {   // phase 2: vector-zero this block's scratch region for the next call
        float4* r4 = (float4*)region;      // 1024 float4
        #pragma unroll
        for (int j = 0; j < 4; j++)
            r4[j * 256 + tid] = make_float4(0.f, 0.f, 0.f, 0.f);
    }

    {   // phase 3: coalesced-in-n stores to the output layout + bias
        const int nn = tid & 63, o0 = tid >> 6;
        float* dstb = out + (size_t)b * COUT_ * N_ + n0 + nn;
        #pragma unroll
        for (int j = 0; j < 16; j++) {
            int o = o0 * 16 + j;
            dstb[(size_t)o * N_] = s[nn * 65 + o] + bias[o];
        }
    }
}

// ---------- launch ----------
extern "C" void kernel_launch(void* const* d_in, const int* in_sizes, int n_in,
                              void* d_out, int out_size)
{
    // All six inputs have distinct element counts -> match by size.
    const float *feat = nullptr, *theta = nullptr, *wb = nullptr,
                *pos = nullptr, *bias = nullptr;
    const int* nbh = nullptr;
    for (int i = 0; i < n_in; i++) {
        switch (in_sizes[i]) {
            case B_ * CIN_ * N_:    feat  = (const float*)d_in[i]; break; // 4194304
            case 3 * CIN_ * COUT_:  theta = (const float*)d_in[i]; break; // 12288
            case CIN_ * COUT_:      wb    = (const float*)d_in[i]; break; // 4096
            case B_ * K_ * N_:      nbh   = (const int*)  d_in[i]; break; // 524288
            case B_ * 3 * N_:       pos   = (const float*)d_in[i]; break; // 196608
            case COUT_:             bias  = (const float*)d_in[i]; break; // 64
        }
    }

    const int smem_bytes = (4 * CIN_ * COUT_ + CIN_ * TILE_ + TILE_ * K_ * 4)
                           * (int)sizeof(float);   // 77824 B
    cudaFuncSetAttribute(flexconv_main_kernel,
                         cudaFuncAttributeMaxDynamicSharedMemorySize, smem_bytes);

    // 1) persistent fused compute + scatter (scratch is zero on entry)
    flexconv_main_kernel<<<GRID_MAIN_, 256, smem_bytes>>>(feat, theta, wb, nbh, pos);

    // 2) transpose + bias into the harness output, re-zero scratch
    finalize_kernel<<<dim3(N_ / 64, B_), 256>>>((float*)d_out, bias);
}